// round 4
// baseline (speedup 1.0000x reference)
#include <cuda_runtime.h>
#include <math.h>

#define SEQ   512
#define BATCH 64
#define HID   1024
#define NG    4096                 // 4*HID
#define MROWS (SEQ * BATCH)        // 32768
#define STEP_CTAS 128

// ---- scratch (static device globals: allocation-free per harness rules) ----
__device__ float g_G[(size_t)MROWS * NG];     // 536 MB: G0 then reused for G1
__device__ float g_h0[(size_t)MROWS * HID];   // 134 MB: layer-0 h sequence
__device__ float g_c[2 * BATCH * HID];        // running cell states

// ---- software grid barrier (all STEP_CTAS co-resident: 128 <= 148 SMs) ----
__device__ unsigned int g_bar_count = 0;
__device__ volatile unsigned int g_bar_gen = 0;

__device__ __forceinline__ void grid_barrier()
{
    __syncthreads();
    if (threadIdx.x == 0) {
        __threadfence();
        unsigned gen = g_bar_gen;                       // read BEFORE arriving
        unsigned arrived = atomicAdd(&g_bar_count, 1u);
        if (arrived == STEP_CTAS - 1) {
            g_bar_count = 0;
            __threadfence();
            g_bar_gen = gen + 1;
        } else {
            while (g_bar_gen == gen) { }
        }
    }
    __syncthreads();
}

// ============================================================================
// Big GEMM: g_G[m,n] = A[m,0:1024] @ W[0:1024, n] + b1[n] + b2[n]
// A = x (use_h0=0) or g_h0 (use_h0=1).  M=32768, N=4096, K=1024.
// Tile 128x128, BK=8, 256 threads, 8x8 per thread.
// ============================================================================
__global__ __launch_bounds__(256) void gemm_bias_kernel(
    const float* __restrict__ Ain, int use_h0,
    const float* __restrict__ W,
    const float* __restrict__ b1,
    const float* __restrict__ b2)
{
    const float* A = use_h0 ? g_h0 : Ain;

    __shared__ float As[8][128];   // transposed A tile: As[k][m]
    __shared__ float Bs[8][128];   // Bs[k][n]

    const int tid = threadIdx.x;
    const int tx  = tid & 15;      // n-thread (8 cols each)
    const int ty  = tid >> 4;      // m-thread (8 rows each)
    const int n0  = blockIdx.x * 128;
    const int m0  = blockIdx.y * 128;

    const int ar  = tid >> 1;          // 0..127 A tile row
    const int akq = (tid & 1) * 4;     // 0 or 4: k quad
    const int bk  = tid >> 5;          // 0..7   B tile k row
    const int bc  = (tid & 31) * 4;    // 0..124 B col quad

    float acc[8][8] = {};

    for (int k0 = 0; k0 < HID; k0 += 8) {
        float4 av = *(const float4*)&A[(size_t)(m0 + ar) * HID + k0 + akq];
        float4 bv = *(const float4*)&W[(size_t)(k0 + bk) * NG + n0 + bc];
        __syncthreads();
        As[akq + 0][ar] = av.x;
        As[akq + 1][ar] = av.y;
        As[akq + 2][ar] = av.z;
        As[akq + 3][ar] = av.w;
        *(float4*)&Bs[bk][bc] = bv;
        __syncthreads();
#pragma unroll
        for (int kk = 0; kk < 8; kk++) {
            float a[8], b[8];
            *(float4*)&a[0] = *(const float4*)&As[kk][ty * 8];
            *(float4*)&a[4] = *(const float4*)&As[kk][ty * 8 + 4];
            *(float4*)&b[0] = *(const float4*)&Bs[kk][tx * 8];
            *(float4*)&b[4] = *(const float4*)&Bs[kk][tx * 8 + 4];
#pragma unroll
            for (int i = 0; i < 8; i++)
#pragma unroll
                for (int j = 0; j < 8; j++)
                    acc[i][j] += a[i] * b[j];
        }
    }

#pragma unroll
    for (int i = 0; i < 8; i++) {
        int m = m0 + ty * 8 + i;
        int n = n0 + tx * 8;
        float4 o0, o1;
        o0.x = acc[i][0] + b1[n + 0] + b2[n + 0];
        o0.y = acc[i][1] + b1[n + 1] + b2[n + 1];
        o0.z = acc[i][2] + b1[n + 2] + b2[n + 2];
        o0.w = acc[i][3] + b1[n + 3] + b2[n + 3];
        o1.x = acc[i][4] + b1[n + 4] + b2[n + 4];
        o1.y = acc[i][5] + b1[n + 5] + b2[n + 5];
        o1.z = acc[i][6] + b1[n + 6] + b2[n + 6];
        o1.w = acc[i][7] + b1[n + 7] + b2[n + 7];
        *(float4*)&g_G[(size_t)m * NG + n]     = o0;
        *(float4*)&g_G[(size_t)m * NG + n + 4] = o1;
    }
}

// ============================================================================
// Persistent recurrence for one layer: all SEQ steps in ONE kernel.
// Per step:
//   gates[b,n] = g_G[t,b,n] + h_prev[b,:] @ Whh[:,n]      (t>0)
//   i,f,o,g = split(gates); c = sig(f)*c + sig(i)*tanh(g); h = sig(o)*tanh(c)
// Grid: 128 CTAs, each owns 8 hidden columns (all 4 gates for them).
// Grid barrier between steps makes h_out(t-1) visible before step t.
// ============================================================================
__global__ __launch_bounds__(256) void lstm_layer_kernel(
    const float* __restrict__ Whh, int layer, float* __restrict__ dout)
{
    float* hseq = (layer == 0) ? g_h0 : dout;
    float* c_st = g_c + layer * BATCH * HID;

    __shared__ float As[16][68];   // h_prev tile (transposed), padded
    __shared__ float Bs[16][32];   // Whh tile (32 gate-cols of this CTA)
    __shared__ float Sg[32][65];   // gate exchange: [gate-col v][batch]

    const int tid = threadIdx.x;
    const int tx  = tid & 31;          // gate-col v: gate = v>>3, j = v&7
    const int ty  = tid >> 5;          // 0..7
    const int c0  = blockIdx.x * 8;    // hidden-col base
    const int m0  = ty * 8;            // batch base for this thread

    const int lrow = tid >> 2;          // 0..63 batch row
    const int lkq  = (tid & 3) * 4;
    const int bkk  = tid >> 4;          // 0..15 k row
    const int bv   = tid & 15;          // loads cols bv and bv+16
    const int g1 = bv >> 3,        j1 = bv & 7;
    const int g2 = (bv + 16) >> 3, j2 = (bv + 16) & 7;

    for (int t = 0; t < SEQ; t++) {
        const float* G      = g_G + (size_t)t * BATCH * NG;
        const float* h_prev = hseq + (size_t)(t - 1) * BATCH * HID;
        float*       h_out  = hseq + (size_t)t * BATCH * HID;

        float acc[8] = {};

        if (t > 0) {
            for (int k0 = 0; k0 < HID; k0 += 16) {
                float4 av = *(const float4*)&h_prev[(size_t)lrow * HID + k0 + lkq];
                float w1 = Whh[(size_t)(k0 + bkk) * NG + g1 * HID + c0 + j1];
                float w2 = Whh[(size_t)(k0 + bkk) * NG + g2 * HID + c0 + j2];
                __syncthreads();
                As[lkq + 0][lrow] = av.x;
                As[lkq + 1][lrow] = av.y;
                As[lkq + 2][lrow] = av.z;
                As[lkq + 3][lrow] = av.w;
                Bs[bkk][bv]      = w1;
                Bs[bkk][bv + 16] = w2;
                __syncthreads();
#pragma unroll
                for (int kk = 0; kk < 16; kk++) {
                    float  b  = Bs[kk][tx];
                    float4 a0 = *(const float4*)&As[kk][m0];
                    float4 a1 = *(const float4*)&As[kk][m0 + 4];
                    acc[0] += a0.x * b; acc[1] += a0.y * b;
                    acc[2] += a0.z * b; acc[3] += a0.w * b;
                    acc[4] += a1.x * b; acc[5] += a1.y * b;
                    acc[6] += a1.z * b; acc[7] += a1.w * b;
                }
            }
        }

        // exchange partial gates so each thread sees all 4 gates of (b, col)
        __syncthreads();
#pragma unroll
        for (int i = 0; i < 8; i++) Sg[tx][m0 + i] = acc[i];
        __syncthreads();

        // cell update: 512 (b, j) pairs, 2 per thread
        for (int p = tid; p < BATCH * 8; p += 256) {
            int b = p >> 3, j = p & 7;
            const float* Gb = G + (size_t)b * NG + c0 + j;
            float ig = Sg[0 * 8 + j][b] + Gb[0 * HID];
            float fg = Sg[1 * 8 + j][b] + Gb[1 * HID];
            float og = Sg[2 * 8 + j][b] + Gb[2 * HID];
            float gg = Sg[3 * 8 + j][b] + Gb[3 * HID];

            float si = 1.f / (1.f + __expf(-ig));
            float sf = 1.f / (1.f + __expf(-fg));
            float so = 1.f / (1.f + __expf(-og));
            float tg = tanhf(gg);

            int idx = b * HID + c0 + j;
            float cp = (t == 0) ? 0.f : c_st[idx];
            float cn = sf * cp + si * tg;
            float h  = so * tanhf(cn);
            c_st[idx]  = cn;
            h_out[idx] = h;
        }

        grid_barrier();   // h_out(t) globally visible before step t+1
    }
}

// ============================================================================
// Copy h_n / c_n into the tail of d_out.
// Layout: [output 512*64*1024][h_n 2*64*1024][c_n 2*64*1024]
// ============================================================================
__global__ void finalize_kernel(float* __restrict__ dout)
{
    int i = blockIdx.x * blockDim.x + threadIdx.x;   // 0 .. 262143
    const size_t OUT_TAIL = (size_t)SEQ * BATCH * HID;
    int seg = i >> 16;          // 0: h_n0, 1: h_n1, 2: c_n0, 3: c_n1
    int off = i & 65535;
    float v;
    if (seg == 0)      v = g_h0[(size_t)(SEQ - 1) * BATCH * HID + off];
    else if (seg == 1) v = dout[(size_t)(SEQ - 1) * BATCH * HID + off];
    else if (seg == 2) v = g_c[off];
    else               v = g_c[BATCH * HID + off];
    dout[OUT_TAIL + (size_t)seg * 65536 + off] = v;
}

// ============================================================================
extern "C" void kernel_launch(void* const* d_in, const int* in_sizes, int n_in,
                              void* d_out, int out_size)
{
    const float* x    = (const float*)d_in[0];
    const float* Wih0 = (const float*)d_in[1];
    const float* bih0 = (const float*)d_in[2];
    const float* Whh0 = (const float*)d_in[3];
    const float* bhh0 = (const float*)d_in[4];
    const float* Wih1 = (const float*)d_in[5];
    const float* bih1 = (const float*)d_in[6];
    const float* Whh1 = (const float*)d_in[7];
    const float* bhh1 = (const float*)d_in[8];
    float* out = (float*)d_out;

    dim3 gg(NG / 128, MROWS / 128);   // 32 x 256 CTAs

    // Phase 1: G0 = x @ Wih0 + bih0 + bhh0
    gemm_bias_kernel<<<gg, 256>>>(x, 0, Wih0, bih0, bhh0);

    // Phase 2: layer-0 recurrence (persistent, one node)
    lstm_layer_kernel<<<STEP_CTAS, 256>>>(Whh0, 0, out);

    // Phase 3: G1 = h0_seq @ Wih1 + bih1 + bhh1
    gemm_bias_kernel<<<gg, 256>>>(nullptr, 1, Wih1, bih1, bhh1);

    // Phase 4: layer-1 recurrence (h sequence = output, directly into d_out)
    lstm_layer_kernel<<<STEP_CTAS, 256>>>(Whh1, 1, out);

    // Phase 5: h_n / c_n
    finalize_kernel<<<1024, 256>>>(out);
}

// round 9
// speedup vs baseline: 1.4667x; 1.4667x over previous
#include <cuda_runtime.h>
#include <cuda_bf16.h>
#include <cstdint>
#include <math.h>

#define SEQ   512
#define BATCH 64
#define HID   1024
#define NG    4096                 // 4*HID
#define MROWS (SEQ * BATCH)        // 32768
#define STEP_CTAS 128

// ---- scratch (static device globals: allocation-free per harness rules) ----
__device__ float g_G[(size_t)MROWS * NG];        // 536 MB: G0 then reused for G1
__device__ float g_h0[(size_t)MROWS * HID];      // 134 MB: layer-0 h sequence (fp32)
__device__ float g_c[2 * BATCH * HID];           // running cell states
__device__ __nv_bfloat16 g_xhi[(size_t)MROWS * HID];
__device__ __nv_bfloat16 g_xlo[(size_t)MROWS * HID];
__device__ __nv_bfloat16 g_h0hi[(size_t)MROWS * HID];
__device__ __nv_bfloat16 g_h0lo[(size_t)MROWS * HID];
__device__ __nv_bfloat16 g_w0hiT[(size_t)NG * HID];   // Wih0^T [n][k]
__device__ __nv_bfloat16 g_w0loT[(size_t)NG * HID];
__device__ __nv_bfloat16 g_w1hiT[(size_t)NG * HID];   // Wih1^T [n][k]
__device__ __nv_bfloat16 g_w1loT[(size_t)NG * HID];

// ---- software grid barrier (all STEP_CTAS co-resident: 128 <= 148 SMs) ----
__device__ unsigned int g_bar_count = 0;
__device__ volatile unsigned int g_bar_gen = 0;

__device__ __forceinline__ void grid_barrier()
{
    __syncthreads();
    if (threadIdx.x == 0) {
        __threadfence();
        unsigned gen = g_bar_gen;                       // read BEFORE arriving
        unsigned arrived = atomicAdd(&g_bar_count, 1u);
        if (arrived == STEP_CTAS - 1) {
            g_bar_count = 0;
            __threadfence();
            g_bar_gen = gen + 1;
        } else {
            while (g_bar_gen == gen) { }
        }
    }
    __syncthreads();
}

// ============================================================================
// Conversion kernels
// ============================================================================
__global__ void split_kernel(const float* __restrict__ src,
                             __nv_bfloat16* __restrict__ hi,
                             __nv_bfloat16* __restrict__ lo, int n)
{
    int i = blockIdx.x * blockDim.x + threadIdx.x;
    if (i < n) {
        float v = src[i];
        __nv_bfloat16 h = __float2bfloat16(v);
        hi[i] = h;
        lo[i] = __float2bfloat16(v - __bfloat162float(h));
    }
}

// W [1024][4096] fp32  ->  WT hi/lo bf16 [4096][1024]
__global__ void transpose_split_kernel(const float* __restrict__ W,
                                       __nv_bfloat16* __restrict__ hiT,
                                       __nv_bfloat16* __restrict__ loT)
{
    __shared__ float tile[32][33];
    int tx = threadIdx.x, ty = threadIdx.y;
    int nb = blockIdx.x * 32;       // n base
    int kb = blockIdx.y * 32;       // k base
#pragma unroll
    for (int i = ty; i < 32; i += 8)
        tile[i][tx] = W[(size_t)(kb + i) * NG + nb + tx];
    __syncthreads();
#pragma unroll
    for (int i = ty; i < 32; i += 8) {
        float v = tile[tx][i];
        __nv_bfloat16 h = __float2bfloat16(v);
        size_t o = (size_t)(nb + i) * HID + kb + tx;
        hiT[o] = h;
        loT[o] = __float2bfloat16(v - __bfloat162float(h));
    }
}

// ============================================================================
// Tensor-core big GEMM (split-bf16, 3 MMA): g_G = A @ W + b1 + b2
// A: hi/lo bf16 [M=32768][K=1024];  W^T: hi/lo bf16 [N=4096][K=1024]
// CTA tile 128x128, BK=32, 8 warps (4m x 2n), warp tile 32x64.
// 2-stage cp.async pipeline, 80KB dynamic smem.
// smem rows padded to 40 bf16 (80B) -> conflict-free ldmatrix.
// ============================================================================
#define GSTAGE 40960
#define AHOFF  0
#define ALOFF  10240
#define BHOFF  20480
#define BLOFF  30720

__device__ __forceinline__ void cp16(uint32_t dst, const void* src)
{
    asm volatile("cp.async.cg.shared.global [%0], [%1], 16;" :: "r"(dst), "l"(src));
}
__device__ __forceinline__ void ldmx4(uint32_t* r, uint32_t addr)
{
    asm volatile("ldmatrix.sync.aligned.m8n8.x4.shared.b16 {%0,%1,%2,%3}, [%4];"
        : "=r"(r[0]), "=r"(r[1]), "=r"(r[2]), "=r"(r[3]) : "r"(addr));
}
__device__ __forceinline__ void mma_bf16(float* d, const uint32_t* a,
                                         uint32_t b0, uint32_t b1)
{
    asm volatile("mma.sync.aligned.m16n8k16.row.col.f32.bf16.bf16.f32 "
        "{%0,%1,%2,%3}, {%4,%5,%6,%7}, {%8,%9}, {%0,%1,%2,%3};"
        : "+f"(d[0]), "+f"(d[1]), "+f"(d[2]), "+f"(d[3])
        : "r"(a[0]), "r"(a[1]), "r"(a[2]), "r"(a[3]), "r"(b0), "r"(b1));
}

__device__ __forceinline__ void ld_stage_gemm(uint32_t base,
    const __nv_bfloat16* __restrict__ Ahi, const __nv_bfloat16* __restrict__ Alo,
    const __nv_bfloat16* __restrict__ BhiT, const __nv_bfloat16* __restrict__ BloT,
    int m0, int n0, int k0, int tid)
{
#pragma unroll
    for (int e = 0; e < 2; e++) {
        int g   = tid * 2 + e;
        int row = g >> 2;
        int seg = (g & 3) * 8;              // bf16 elems
        uint32_t doff = row * 80 + seg * 2; // bytes
        size_t soA = (size_t)(m0 + row) * HID + k0 + seg;
        size_t soB = (size_t)(n0 + row) * HID + k0 + seg;
        cp16(base + AHOFF + doff, Ahi  + soA);
        cp16(base + ALOFF + doff, Alo  + soA);
        cp16(base + BHOFF + doff, BhiT + soB);
        cp16(base + BLOFF + doff, BloT + soB);
    }
}

__global__ __launch_bounds__(256, 1) void gemm_mma_kernel(
    const __nv_bfloat16* __restrict__ Ahi, const __nv_bfloat16* __restrict__ Alo,
    const __nv_bfloat16* __restrict__ BhiT, const __nv_bfloat16* __restrict__ BloT,
    const float* __restrict__ b1, const float* __restrict__ b2)
{
    extern __shared__ char smem_dyn[];
    const uint32_t sb = (uint32_t)__cvta_generic_to_shared(smem_dyn);

    const int tid  = threadIdx.x;
    const int lane = tid & 31;
    const int wid  = tid >> 5;
    const int wm   = wid & 3;           // 0..3  (m band of 32)
    const int wn   = wid >> 2;          // 0..1  (n band of 64)
    const int m0   = blockIdx.y * 128;
    const int n0   = blockIdx.x * 128;

    float acc[2][8][4];
#pragma unroll
    for (int a = 0; a < 2; a++)
#pragma unroll
        for (int b = 0; b < 8; b++)
#pragma unroll
            for (int c = 0; c < 4; c++) acc[a][b][c] = 0.f;

    const int matq = lane >> 3;   // which 8x8 matrix this lane addresses
    const int r8   = lane & 7;

    ld_stage_gemm(sb, Ahi, Alo, BhiT, BloT, m0, n0, 0, tid);
    asm volatile("cp.async.commit_group;");

#pragma unroll 1
    for (int c = 0; c < 32; c++) {
        if (c + 1 < 32) {
            ld_stage_gemm(sb + ((c + 1) & 1) * GSTAGE,
                          Ahi, Alo, BhiT, BloT, m0, n0, (c + 1) * 32, tid);
            asm volatile("cp.async.commit_group;");
            asm volatile("cp.async.wait_group 1;");
        } else {
            asm volatile("cp.async.wait_group 0;");
        }
        __syncthreads();
        const uint32_t st = sb + (c & 1) * GSTAGE;

#pragma unroll
        for (int kk = 0; kk < 32; kk += 16) {
            uint32_t ah[2][4], al[2][4];
#pragma unroll
            for (int mt = 0; mt < 2; mt++) {
                int rowA = wm * 32 + mt * 16 + (matq & 1) * 8 + r8;
                int colA = kk + (matq >> 1) * 8;
                uint32_t ad = st + rowA * 80 + colA * 2;
                ldmx4(ah[mt], ad + AHOFF);
                ldmx4(al[mt], ad + ALOFF);
            }
            uint32_t bh[4][4], bl[4][4];
#pragma unroll
            for (int ng = 0; ng < 4; ng++) {
                int rowB = wn * 64 + ng * 16 + (matq >> 1) * 8 + r8;
                int colB = kk + (matq & 1) * 8;
                uint32_t bd = st + rowB * 80 + colB * 2;
                ldmx4(bh[ng], bd + BHOFF);
                ldmx4(bl[ng], bd + BLOFF);
            }
#pragma unroll
            for (int mt = 0; mt < 2; mt++)
#pragma unroll
                for (int ng = 0; ng < 4; ng++)
#pragma unroll
                    for (int hf = 0; hf < 2; hf++) {
                        int nt = ng * 2 + hf;
                        mma_bf16(acc[mt][nt], ah[mt], bh[ng][hf * 2], bh[ng][hf * 2 + 1]);
                        mma_bf16(acc[mt][nt], ah[mt], bl[ng][hf * 2], bl[ng][hf * 2 + 1]);
                        mma_bf16(acc[mt][nt], al[mt], bh[ng][hf * 2], bh[ng][hf * 2 + 1]);
                    }
        }
        __syncthreads();
    }

    // epilogue: add biases, store fp32
#pragma unroll
    for (int mt = 0; mt < 2; mt++)
#pragma unroll
        for (int nt = 0; nt < 8; nt++) {
            int row = m0 + wm * 32 + mt * 16 + (lane >> 2);
            int col = n0 + wn * 64 + nt * 8 + (lane & 3) * 2;
            float bs0 = b1[col] + b2[col];
            float bs1 = b1[col + 1] + b2[col + 1];
            float2 v0 = make_float2(acc[mt][nt][0] + bs0, acc[mt][nt][1] + bs1);
            float2 v1 = make_float2(acc[mt][nt][2] + bs0, acc[mt][nt][3] + bs1);
            *(float2*)&g_G[(size_t)row * NG + col]       = v0;
            *(float2*)&g_G[(size_t)(row + 8) * NG + col] = v1;
        }
}

// ============================================================================
// Persistent recurrence for one layer (fp32 SIMT, split-K, 4x4 thread tile).
// 128 CTAs x 256 threads; CTA owns 8 hidden cols (32 gate cols, v = q*8+j).
// kg = tid>>7 handles k in [kg*512, kg*512+512).
// Layer 0 additionally emits h as bf16 hi/lo for the layer-1 tensor GEMM.
// ============================================================================
__global__ __launch_bounds__(256) void lstm_layer_kernel(
    const float* __restrict__ Whh, int layer, float* __restrict__ dout)
{
    float* hseq = (layer == 0) ? g_h0 : dout;
    float* c_st = g_c + layer * BATCH * HID;

    __shared__ float As[2][32][68];   // [kg][k][m]   h tile, transposed
    __shared__ float Ws[2][32][36];   // [kg][k][v]   Whh tile
    __shared__ float Sred[64][36];    // gates: [batch][v]

    const int tid = threadIdx.x;
    const int kg  = tid >> 7;          // k group 0/1
    const int tl  = tid & 127;
    const int tm  = tl >> 3;           // 0..15 -> m0 = tm*4
    const int tn  = tl & 7;            // 0..7  -> v0 = tn*4
    const int c0  = blockIdx.x * 8;    // hidden-col base

    for (int t = 0; t < SEQ; t++) {
        const float* G      = g_G + (size_t)t * BATCH * NG;
        const float* h_prev = hseq + (size_t)(t - 1) * BATCH * HID;
        float*       h_out  = hseq + (size_t)t * BATCH * HID;

        float acc[4][4];
#pragma unroll
        for (int i = 0; i < 4; i++)
#pragma unroll
            for (int j = 0; j < 4; j++) acc[i][j] = 0.f;

        if (t > 0) {
#pragma unroll 1
            for (int kc = 0; kc < 512; kc += 32) {
                const int kbase = kg * 512 + kc;
                __syncthreads();
                // h tile: As[kg][k][m] = h_prev[m][kbase+k]
#pragma unroll
                for (int p = 0; p < 4; p++) {
                    int m  = tl & 63;
                    int kq = (tl >> 6) + p * 2;        // 0..7
                    float4 av = *(const float4*)&h_prev[(size_t)m * HID + kbase + kq * 4];
                    As[kg][kq * 4 + 0][m] = av.x;
                    As[kg][kq * 4 + 1][m] = av.y;
                    As[kg][kq * 4 + 2][m] = av.z;
                    As[kg][kq * 4 + 3][m] = av.w;
                }
                // W tile: Ws[kg][k][v] = Whh[kbase+k][(v>>3)*1024 + c0 + (v&7)]
#pragma unroll
                for (int p = 0; p < 8; p++) {
                    int idx = p * 128 + tl;
                    int k = idx >> 5;
                    int v = idx & 31;
                    Ws[kg][k][v] =
                        Whh[(size_t)(kbase + k) * NG + (v >> 3) * HID + c0 + (v & 7)];
                }
                __syncthreads();
#pragma unroll
                for (int kk = 0; kk < 32; kk++) {
                    float4 a4 = *(const float4*)&As[kg][kk][tm * 4];
                    float4 b4 = *(const float4*)&Ws[kg][kk][tn * 4];
                    float am[4] = {a4.x, a4.y, a4.z, a4.w};
                    float bn[4] = {b4.x, b4.y, b4.z, b4.w};
#pragma unroll
                    for (int i = 0; i < 4; i++)
#pragma unroll
                        for (int j = 0; j < 4; j++)
                            acc[i][j] += am[i] * bn[j];
                }
            }
            // reduce the two k-groups into Sred
            __syncthreads();
            if (kg == 1) {
#pragma unroll
                for (int i = 0; i < 4; i++)
#pragma unroll
                    for (int j = 0; j < 4; j++)
                        Sred[tm * 4 + i][tn * 4 + j] = acc[i][j];
            }
            __syncthreads();
            if (kg == 0) {
#pragma unroll
                for (int i = 0; i < 4; i++)
#pragma unroll
                    for (int j = 0; j < 4; j++)
                        Sred[tm * 4 + i][tn * 4 + j] += acc[i][j];
            }
            __syncthreads();
        }

        // cell update: 512 (b, j) pairs, 2 per thread
#pragma unroll
        for (int p = tid; p < BATCH * 8; p += 256) {
            int b = p >> 3, j = p & 7;
            const float* Gb = G + (size_t)b * NG + c0 + j;
            float ig = Gb[0 * HID];
            float fg = Gb[1 * HID];
            float og = Gb[2 * HID];
            float gg = Gb[3 * HID];
            if (t > 0) {
                ig += Sred[b][j];
                fg += Sred[b][8 + j];
                og += Sred[b][16 + j];
                gg += Sred[b][24 + j];
            }
            float si = 1.f / (1.f + __expf(-ig));
            float sf = 1.f / (1.f + __expf(-fg));
            float so = 1.f / (1.f + __expf(-og));
            float tg = tanhf(gg);

            int idx = b * HID + c0 + j;
            float cp = (t == 0) ? 0.f : c_st[idx];
            float cn = sf * cp + si * tg;
            float h  = so * tanhf(cn);
            c_st[idx]  = cn;
            h_out[idx] = h;

            if (layer == 0) {
                size_t o = (size_t)t * BATCH * HID + idx;
                __nv_bfloat16 hh = __float2bfloat16(h);
                g_h0hi[o] = hh;
                g_h0lo[o] = __float2bfloat16(h - __bfloat162float(hh));
            }
        }

        grid_barrier();   // h_out(t) globally visible before step t+1
    }
}

// ============================================================================
// Copy h_n / c_n into the tail of d_out.
// Layout: [output 512*64*1024][h_n 2*64*1024][c_n 2*64*1024]
// ============================================================================
__global__ void finalize_kernel(float* __restrict__ dout)
{
    int i = blockIdx.x * blockDim.x + threadIdx.x;   // 0 .. 262143
    const size_t OUT_TAIL = (size_t)SEQ * BATCH * HID;
    int seg = i >> 16;          // 0: h_n0, 1: h_n1, 2: c_n0, 3: c_n1
    int off = i & 65535;
    float v;
    if (seg == 0)      v = g_h0[(size_t)(SEQ - 1) * BATCH * HID + off];
    else if (seg == 1) v = dout[(size_t)(SEQ - 1) * BATCH * HID + off];
    else if (seg == 2) v = g_c[off];
    else               v = g_c[BATCH * HID + off];
    dout[OUT_TAIL + (size_t)seg * 65536 + off] = v;
}

// ============================================================================
extern "C" void kernel_launch(void* const* d_in, const int* in_sizes, int n_in,
                              void* d_out, int out_size)
{
    const float* x    = (const float*)d_in[0];
    const float* Wih0 = (const float*)d_in[1];
    const float* bih0 = (const float*)d_in[2];
    const float* Whh0 = (const float*)d_in[3];
    const float* bhh0 = (const float*)d_in[4];
    const float* Wih1 = (const float*)d_in[5];
    const float* bih1 = (const float*)d_in[6];
    const float* Whh1 = (const float*)d_in[7];
    const float* bhh1 = (const float*)d_in[8];
    float* out = (float*)d_out;

    cudaFuncSetAttribute(gemm_mma_kernel,
                         cudaFuncAttributeMaxDynamicSharedMemorySize, 2 * GSTAGE);

    // device-global symbol addresses (host side)
    __nv_bfloat16 *xhi, *xlo, *h0hi, *h0lo, *w0h, *w0l, *w1h, *w1l;
    cudaGetSymbolAddress((void**)&xhi,  g_xhi);
    cudaGetSymbolAddress((void**)&xlo,  g_xlo);
    cudaGetSymbolAddress((void**)&h0hi, g_h0hi);
    cudaGetSymbolAddress((void**)&h0lo, g_h0lo);
    cudaGetSymbolAddress((void**)&w0h,  g_w0hiT);
    cudaGetSymbolAddress((void**)&w0l,  g_w0loT);
    cudaGetSymbolAddress((void**)&w1h,  g_w1hiT);
    cudaGetSymbolAddress((void**)&w1l,  g_w1loT);

    const int NX = MROWS * HID;
    dim3 tg(NG / 32, HID / 32);          // transpose grid
    dim3 gg(NG / 128, MROWS / 128);      // gemm grid: 32 x 256

    // Phase 0: conversions
    split_kernel<<<NX / 256, 256>>>(x, xhi, xlo, NX);
    transpose_split_kernel<<<tg, dim3(32, 8)>>>(Wih0, w0h, w0l);
    transpose_split_kernel<<<tg, dim3(32, 8)>>>(Wih1, w1h, w1l);

    // Phase 1: G0 = x @ Wih0 + bih0 + bhh0   (tensor cores)
    gemm_mma_kernel<<<gg, 256, 2 * GSTAGE>>>(xhi, xlo, w0h, w0l, bih0, bhh0);

    // Phase 2: layer-0 recurrence (persistent)
    lstm_layer_kernel<<<STEP_CTAS, 256>>>(Whh0, 0, out);

    // Phase 3: G1 = h0_seq @ Wih1 + bih1 + bhh1   (tensor cores)
    gemm_mma_kernel<<<gg, 256, 2 * GSTAGE>>>(h0hi, h0lo, w1h, w1l, bih1, bhh1);

    // Phase 4: layer-1 recurrence (directly into d_out)
    lstm_layer_kernel<<<STEP_CTAS, 256>>>(Whh1, 1, out);

    // Phase 5: h_n / c_n
    finalize_kernel<<<1024, 256>>>(out);
}

// round 10
// speedup vs baseline: 3.2819x; 2.2376x over previous
#include <cuda_runtime.h>
#include <cuda_bf16.h>
#include <cstdint>
#include <math.h>

#define SEQ   512
#define BATCH 64
#define HID   1024
#define NG    4096                 // 4*HID
#define MROWS (SEQ * BATCH)        // 32768
#define STEP_CTAS 128

// ---- scratch (static device globals: allocation-free per harness rules) ----
__device__ float g_G[(size_t)MROWS * NG];        // 536 MB: G0 then reused for G1
__device__ float g_h0[(size_t)MROWS * HID];      // layer-0 h fp32 (only t=511 written)
__device__ float g_c[2 * BATCH * HID];           // final cell states
__device__ __nv_bfloat16 g_xhi[(size_t)MROWS * HID];
__device__ __nv_bfloat16 g_xlo[(size_t)MROWS * HID];
__device__ __nv_bfloat16 g_h0hi[(size_t)MROWS * HID];   // layer-0 h seq (bf16 split)
__device__ __nv_bfloat16 g_h0lo[(size_t)MROWS * HID];
__device__ __nv_bfloat16 g_h1hi[2 * BATCH * HID];       // layer-1 h ping-pong
__device__ __nv_bfloat16 g_h1lo[2 * BATCH * HID];
__device__ __nv_bfloat16 g_w0hiT[(size_t)NG * HID];     // Wih0^T [n][k]
__device__ __nv_bfloat16 g_w0loT[(size_t)NG * HID];
__device__ __nv_bfloat16 g_w1hiT[(size_t)NG * HID];     // Wih1^T [n][k]
__device__ __nv_bfloat16 g_w1loT[(size_t)NG * HID];
__device__ __nv_bfloat16 g_wh0hiT[(size_t)NG * HID];    // Whh0^T [n][k]
__device__ __nv_bfloat16 g_wh0loT[(size_t)NG * HID];
__device__ __nv_bfloat16 g_wh1hiT[(size_t)NG * HID];    // Whh1^T [n][k]
__device__ __nv_bfloat16 g_wh1loT[(size_t)NG * HID];

// ---- software grid barrier (all STEP_CTAS co-resident: 128 <= 148 SMs) ----
__device__ unsigned int g_bar_count = 0;
__device__ volatile unsigned int g_bar_gen = 0;

__device__ __forceinline__ void grid_barrier()
{
    __syncthreads();
    if (threadIdx.x == 0) {
        __threadfence();
        unsigned gen = g_bar_gen;                       // read BEFORE arriving
        unsigned arrived = atomicAdd(&g_bar_count, 1u);
        if (arrived == STEP_CTAS - 1) {
            g_bar_count = 0;
            __threadfence();
            g_bar_gen = gen + 1;
        } else {
            while (g_bar_gen == gen) { }
        }
    }
    __syncthreads();
}

// ============================================================================
// Conversion kernels
// ============================================================================
__global__ void split_kernel(const float* __restrict__ src,
                             __nv_bfloat16* __restrict__ hi,
                             __nv_bfloat16* __restrict__ lo, int n)
{
    int i = blockIdx.x * blockDim.x + threadIdx.x;
    if (i < n) {
        float v = src[i];
        __nv_bfloat16 h = __float2bfloat16(v);
        hi[i] = h;
        lo[i] = __float2bfloat16(v - __bfloat162float(h));
    }
}

// W [1024][4096] fp32  ->  WT hi/lo bf16 [4096][1024]
__global__ void transpose_split_kernel(const float* __restrict__ W,
                                       __nv_bfloat16* __restrict__ hiT,
                                       __nv_bfloat16* __restrict__ loT)
{
    __shared__ float tile[32][33];
    int tx = threadIdx.x, ty = threadIdx.y;
    int nb = blockIdx.x * 32;       // n base
    int kb = blockIdx.y * 32;       // k base
#pragma unroll
    for (int i = ty; i < 32; i += 8)
        tile[i][tx] = W[(size_t)(kb + i) * NG + nb + tx];
    __syncthreads();
#pragma unroll
    for (int i = ty; i < 32; i += 8) {
        float v = tile[tx][i];
        __nv_bfloat16 h = __float2bfloat16(v);
        size_t o = (size_t)(nb + i) * HID + kb + tx;
        hiT[o] = h;
        loT[o] = __float2bfloat16(v - __bfloat162float(h));
    }
}

// ============================================================================
// MMA / ldmatrix / cp.async primitives
// ============================================================================
__device__ __forceinline__ void cp16(uint32_t dst, const void* src)
{
    asm volatile("cp.async.cg.shared.global [%0], [%1], 16;" :: "r"(dst), "l"(src));
}
__device__ __forceinline__ void ldmx4(uint32_t* r, uint32_t addr)
{
    asm volatile("ldmatrix.sync.aligned.m8n8.x4.shared.b16 {%0,%1,%2,%3}, [%4];"
        : "=r"(r[0]), "=r"(r[1]), "=r"(r[2]), "=r"(r[3]) : "r"(addr));
}
__device__ __forceinline__ void mma_bf16(float* d, const uint32_t* a,
                                         uint32_t b0, uint32_t b1)
{
    asm volatile("mma.sync.aligned.m16n8k16.row.col.f32.bf16.bf16.f32 "
        "{%0,%1,%2,%3}, {%4,%5,%6,%7}, {%8,%9}, {%0,%1,%2,%3};"
        : "+f"(d[0]), "+f"(d[1]), "+f"(d[2]), "+f"(d[3])
        : "r"(a[0]), "r"(a[1]), "r"(a[2]), "r"(a[3]), "r"(b0), "r"(b1));
}

// ============================================================================
// Tensor-core big GEMM (split-bf16, 3 MMA): g_G = A @ W + b1 + b2
// (unchanged from R9 — verified, tensor pipe 48%)
// ============================================================================
#define GSTAGE 40960
#define AHOFF  0
#define ALOFF  10240
#define BHOFF  20480
#define BLOFF  30720

__device__ __forceinline__ void ld_stage_gemm(uint32_t base,
    const __nv_bfloat16* __restrict__ Ahi, const __nv_bfloat16* __restrict__ Alo,
    const __nv_bfloat16* __restrict__ BhiT, const __nv_bfloat16* __restrict__ BloT,
    int m0, int n0, int k0, int tid)
{
#pragma unroll
    for (int e = 0; e < 2; e++) {
        int g   = tid * 2 + e;
        int row = g >> 2;
        int seg = (g & 3) * 8;              // bf16 elems
        uint32_t doff = row * 80 + seg * 2; // bytes
        size_t soA = (size_t)(m0 + row) * HID + k0 + seg;
        size_t soB = (size_t)(n0 + row) * HID + k0 + seg;
        cp16(base + AHOFF + doff, Ahi  + soA);
        cp16(base + ALOFF + doff, Alo  + soA);
        cp16(base + BHOFF + doff, BhiT + soB);
        cp16(base + BLOFF + doff, BloT + soB);
    }
}

__global__ __launch_bounds__(256, 1) void gemm_mma_kernel(
    const __nv_bfloat16* __restrict__ Ahi, const __nv_bfloat16* __restrict__ Alo,
    const __nv_bfloat16* __restrict__ BhiT, const __nv_bfloat16* __restrict__ BloT,
    const float* __restrict__ b1, const float* __restrict__ b2)
{
    extern __shared__ char smem_dyn[];
    const uint32_t sb = (uint32_t)__cvta_generic_to_shared(smem_dyn);

    const int tid  = threadIdx.x;
    const int lane = tid & 31;
    const int wid  = tid >> 5;
    const int wm   = wid & 3;
    const int wn   = wid >> 2;
    const int m0   = blockIdx.y * 128;
    const int n0   = blockIdx.x * 128;

    float acc[2][8][4];
#pragma unroll
    for (int a = 0; a < 2; a++)
#pragma unroll
        for (int b = 0; b < 8; b++)
#pragma unroll
            for (int c = 0; c < 4; c++) acc[a][b][c] = 0.f;

    const int matq = lane >> 3;
    const int r8   = lane & 7;

    ld_stage_gemm(sb, Ahi, Alo, BhiT, BloT, m0, n0, 0, tid);
    asm volatile("cp.async.commit_group;");

#pragma unroll 1
    for (int c = 0; c < 32; c++) {
        if (c + 1 < 32) {
            ld_stage_gemm(sb + ((c + 1) & 1) * GSTAGE,
                          Ahi, Alo, BhiT, BloT, m0, n0, (c + 1) * 32, tid);
            asm volatile("cp.async.commit_group;");
            asm volatile("cp.async.wait_group 1;");
        } else {
            asm volatile("cp.async.wait_group 0;");
        }
        __syncthreads();
        const uint32_t st = sb + (c & 1) * GSTAGE;

#pragma unroll
        for (int kk = 0; kk < 32; kk += 16) {
            uint32_t ah[2][4], al[2][4];
#pragma unroll
            for (int mt = 0; mt < 2; mt++) {
                int rowA = wm * 32 + mt * 16 + (matq & 1) * 8 + r8;
                int colA = kk + (matq >> 1) * 8;
                uint32_t ad = st + rowA * 80 + colA * 2;
                ldmx4(ah[mt], ad + AHOFF);
                ldmx4(al[mt], ad + ALOFF);
            }
            uint32_t bh[4][4], bl[4][4];
#pragma unroll
            for (int ng = 0; ng < 4; ng++) {
                int rowB = wn * 64 + ng * 16 + (matq >> 1) * 8 + r8;
                int colB = kk + (matq & 1) * 8;
                uint32_t bd = st + rowB * 80 + colB * 2;
                ldmx4(bh[ng], bd + BHOFF);
                ldmx4(bl[ng], bd + BLOFF);
            }
#pragma unroll
            for (int mt = 0; mt < 2; mt++)
#pragma unroll
                for (int ng = 0; ng < 4; ng++)
#pragma unroll
                    for (int hf = 0; hf < 2; hf++) {
                        int nt = ng * 2 + hf;
                        mma_bf16(acc[mt][nt], ah[mt], bh[ng][hf * 2], bh[ng][hf * 2 + 1]);
                        mma_bf16(acc[mt][nt], ah[mt], bl[ng][hf * 2], bl[ng][hf * 2 + 1]);
                        mma_bf16(acc[mt][nt], al[mt], bh[ng][hf * 2], bh[ng][hf * 2 + 1]);
                    }
        }
        __syncthreads();
    }

#pragma unroll
    for (int mt = 0; mt < 2; mt++)
#pragma unroll
        for (int nt = 0; nt < 8; nt++) {
            int row = m0 + wm * 32 + mt * 16 + (lane >> 2);
            int col = n0 + wn * 64 + nt * 8 + (lane & 3) * 2;
            float bs0 = b1[col] + b2[col];
            float bs1 = b1[col + 1] + b2[col + 1];
            float2 v0 = make_float2(acc[mt][nt][0] + bs0, acc[mt][nt][1] + bs1);
            float2 v1 = make_float2(acc[mt][nt][2] + bs0, acc[mt][nt][3] + bs1);
            *(float2*)&g_G[(size_t)row * NG + col]       = v0;
            *(float2*)&g_G[(size_t)(row + 8) * NG + col] = v1;
        }
}

// ============================================================================
// Tensor-core persistent recurrence.
// 128 CTAs x 256 thr (8 warps). CTA owns 8 hidden cols -> 32 gate cols (v=q*8+j).
// Whh slice (hi/lo bf16, [v][k], k=1024) resident in SMEM all 512 steps.
// Per step: stream h_{t-1} (bf16 hi/lo) in 8 double-buffered k128 chunks,
// 3-MMA split-bf16, K split 2x across warp groups, smem reduce, fused cell.
// SMEM map (bytes):
//   WHI 0..66048       (32 rows x 2064B)
//   WLO 66048..132096
//   H   132096..201728 (2 bufs x [hi 17408 | lo 17408], row 272B)
//   SRED 201728..210176 (64 x 33 fp32)
//   CST  210176..212224 (64 x 8 fp32)
// ============================================================================
#define R_WHI  0u
#define R_WLO  66048u
#define R_HB   132096u
#define R_HBUF 34816u
#define R_HLO  17408u
#define R_SRED 201728u
#define R_CST  210176u
#define R_SMEM 212224

__global__ __launch_bounds__(256, 1) void lstm_layer_mma_kernel(
    const __nv_bfloat16* __restrict__ WhiT,   // Whh^T hi [4096][1024]
    const __nv_bfloat16* __restrict__ WloT,
    int layer, float* __restrict__ dout)
{
    extern __shared__ char smem_dyn[];
    const uint32_t sb = (uint32_t)__cvta_generic_to_shared(smem_dyn);
    float* sred = (float*)(smem_dyn + R_SRED);
    float* cst  = (float*)(smem_dyn + R_CST);

    const int tid  = threadIdx.x;
    const int lane = tid & 31;
    const int wid  = tid >> 5;
    const int wm   = wid & 1;           // m half (32)
    const int wn   = (wid >> 1) & 1;    // n half (16 gate cols)
    const int kg   = wid >> 2;          // k group (64 of each 128-chunk)
    const int matq = lane >> 3;
    const int r8   = lane & 7;
    const int c0   = blockIdx.x * 8;    // hidden-col base

    // ---- load Whh slice into smem (one time), rows v=0..31: n=(v>>3)*1024+c0+(v&7)
#pragma unroll 4
    for (int q = 0; q < 32; q++) {
        int id   = q * 256 + tid;       // 0..8191
        int half = id >> 12;            // 0 hi, 1 lo
        int idl  = id & 4095;
        int v    = idl >> 7;            // 0..31
        int seg  = idl & 127;           // 16B segment (8 bf16)
        const __nv_bfloat16* src = (half ? WloT : WhiT)
            + (size_t)((v >> 3) * HID + c0 + (v & 7)) * HID + seg * 8;
        cp16(sb + (half ? R_WLO : R_WHI) + v * 2064 + seg * 16, src);
    }
    asm volatile("cp.async.commit_group;");
    asm volatile("cp.async.wait_group 0;");
    __syncthreads();

    const __nv_bfloat16* hseqHi = (layer == 0) ? g_h0hi : g_h1hi;
    const __nv_bfloat16* hseqLo = (layer == 0) ? g_h0lo : g_h1lo;

#pragma unroll 1
    for (int t = 0; t < SEQ; t++) {
        float acc[2][2][4];
#pragma unroll
        for (int a = 0; a < 2; a++)
#pragma unroll
            for (int b = 0; b < 2; b++)
#pragma unroll
                for (int c = 0; c < 4; c++) acc[a][b][c] = 0.f;

        if (t > 0) {
            const int rdIdx = (layer == 0) ? (t - 1) : ((t - 1) & 1);
            const __nv_bfloat16* hHi = hseqHi + (size_t)rdIdx * BATCH * HID;
            const __nv_bfloat16* hLo = hseqLo + (size_t)rdIdx * BATCH * HID;

            // preload chunk 0 into buf 0
#pragma unroll
            for (int q = 0; q < 8; q++) {
                int id   = q * 256 + tid;
                int half = id >> 10;
                int idl  = id & 1023;
                int row  = idl >> 4;
                int seg  = idl & 15;
                const __nv_bfloat16* src = (half ? hLo : hHi)
                    + (size_t)row * HID + seg * 8;
                cp16(sb + R_HB + (half ? R_HLO : 0u) + row * 272 + seg * 16, src);
            }
            asm volatile("cp.async.commit_group;");

#pragma unroll 1
            for (int c = 0; c < 8; c++) {
                if (c < 7) {
#pragma unroll
                    for (int q = 0; q < 8; q++) {
                        int id   = q * 256 + tid;
                        int half = id >> 10;
                        int idl  = id & 1023;
                        int row  = idl >> 4;
                        int seg  = idl & 15;
                        const __nv_bfloat16* src = (half ? hLo : hHi)
                            + (size_t)row * HID + (c + 1) * 128 + seg * 8;
                        cp16(sb + R_HB + ((c + 1) & 1) * R_HBUF
                             + (half ? R_HLO : 0u) + row * 272 + seg * 16, src);
                    }
                    asm volatile("cp.async.commit_group;");
                    asm volatile("cp.async.wait_group 1;");
                } else {
                    asm volatile("cp.async.wait_group 0;");
                }
                __syncthreads();

                const uint32_t hb = sb + R_HB + (c & 1) * R_HBUF;
#pragma unroll
                for (int kt = 0; kt < 4; kt++) {
                    const int klocal = kg * 64 + kt * 16;       // within chunk
                    const int kglob  = c * 128 + klocal;        // within K=1024
                    uint32_t ah[2][4], al[2][4];
#pragma unroll
                    for (int mt = 0; mt < 2; mt++) {
                        int rowA = wm * 32 + mt * 16 + (matq & 1) * 8 + r8;
                        int colA = klocal + (matq >> 1) * 8;
                        uint32_t ad = hb + rowA * 272 + colA * 2;
                        ldmx4(ah[mt], ad);
                        ldmx4(al[mt], ad + R_HLO);
                    }
                    uint32_t bh[4], bl[4];
                    {
                        int rowB = wn * 16 + (matq >> 1) * 8 + r8;
                        int colB = kglob + (matq & 1) * 8;
                        uint32_t bd = sb + R_WHI + rowB * 2064 + colB * 2;
                        ldmx4(bh, bd);
                        ldmx4(bl, bd + R_WLO);
                    }
#pragma unroll
                    for (int mt = 0; mt < 2; mt++)
#pragma unroll
                        for (int nt = 0; nt < 2; nt++) {
                            mma_bf16(acc[mt][nt], ah[mt], bh[nt * 2], bh[nt * 2 + 1]);
                            mma_bf16(acc[mt][nt], ah[mt], bl[nt * 2], bl[nt * 2 + 1]);
                            mma_bf16(acc[mt][nt], al[mt], bh[nt * 2], bh[nt * 2 + 1]);
                        }
                }
                __syncthreads();
            }

            // reduce the two k-groups into sred
            if (kg == 1) {
#pragma unroll
                for (int mt = 0; mt < 2; mt++)
#pragma unroll
                    for (int nt = 0; nt < 2; nt++) {
                        int r  = wm * 32 + mt * 16 + (lane >> 2);
                        int cc = wn * 16 + nt * 8 + (lane & 3) * 2;
                        sred[r * 33 + cc]           = acc[mt][nt][0];
                        sred[r * 33 + cc + 1]       = acc[mt][nt][1];
                        sred[(r + 8) * 33 + cc]     = acc[mt][nt][2];
                        sred[(r + 8) * 33 + cc + 1] = acc[mt][nt][3];
                    }
            }
            __syncthreads();
            if (kg == 0) {
#pragma unroll
                for (int mt = 0; mt < 2; mt++)
#pragma unroll
                    for (int nt = 0; nt < 2; nt++) {
                        int r  = wm * 32 + mt * 16 + (lane >> 2);
                        int cc = wn * 16 + nt * 8 + (lane & 3) * 2;
                        sred[r * 33 + cc]           += acc[mt][nt][0];
                        sred[r * 33 + cc + 1]       += acc[mt][nt][1];
                        sred[(r + 8) * 33 + cc]     += acc[mt][nt][2];
                        sred[(r + 8) * 33 + cc + 1] += acc[mt][nt][3];
                    }
            }
            __syncthreads();
        }

        // ---- fused cell update: 512 (b,j) pairs, 2 per thread ----
        const int wrIdx = (layer == 0) ? t : (t & 1);
        __nv_bfloat16* hdHi = ((layer == 0) ? g_h0hi : g_h1hi)
                              + (size_t)wrIdx * BATCH * HID;
        __nv_bfloat16* hdLo = ((layer == 0) ? g_h0lo : g_h1lo)
                              + (size_t)wrIdx * BATCH * HID;

#pragma unroll
        for (int p = tid; p < BATCH * 8; p += 256) {
            int b = p >> 3, j = p & 7;
            const float* Gb = g_G + (size_t)t * BATCH * NG + (size_t)b * NG + c0 + j;
            float ig = Gb[0 * HID];
            float fg = Gb[1 * HID];
            float og = Gb[2 * HID];
            float gg = Gb[3 * HID];
            if (t > 0) {
                ig += sred[b * 33 + j];
                fg += sred[b * 33 + 8 + j];
                og += sred[b * 33 + 16 + j];
                gg += sred[b * 33 + 24 + j];
            }
            float si = 1.f / (1.f + __expf(-ig));
            float sf = 1.f / (1.f + __expf(-fg));
            float so = 1.f / (1.f + __expf(-og));
            float tg = tanhf(gg);

            float cp = (t == 0) ? 0.f : cst[b * 8 + j];
            float cn = sf * cp + si * tg;
            float h  = so * tanhf(cn);
            cst[b * 8 + j] = cn;

            int hidx = b * HID + c0 + j;
            __nv_bfloat16 hh = __float2bfloat16(h);
            hdHi[hidx] = hh;
            hdLo[hidx] = __float2bfloat16(h - __bfloat162float(hh));

            if (layer == 1)
                dout[(size_t)(t * BATCH + b) * HID + c0 + j] = h;
            if (t == SEQ - 1) {
                g_c[layer * BATCH * HID + hidx] = cn;
                if (layer == 0)
                    g_h0[(size_t)(t * BATCH + b) * HID + c0 + j] = h;
            }
        }

        grid_barrier();   // h(t) globally visible before step t+1
    }
}

// ============================================================================
// Copy h_n / c_n into the tail of d_out.
// Layout: [output 512*64*1024][h_n 2*64*1024][c_n 2*64*1024]
// ============================================================================
__global__ void finalize_kernel(float* __restrict__ dout)
{
    int i = blockIdx.x * blockDim.x + threadIdx.x;   // 0 .. 262143
    const size_t OUT_TAIL = (size_t)SEQ * BATCH * HID;
    int seg = i >> 16;          // 0: h_n0, 1: h_n1, 2: c_n0, 3: c_n1
    int off = i & 65535;
    float v;
    if (seg == 0)      v = g_h0[(size_t)(SEQ - 1) * BATCH * HID + off];
    else if (seg == 1) v = dout[(size_t)(SEQ - 1) * BATCH * HID + off];
    else if (seg == 2) v = g_c[off];
    else               v = g_c[BATCH * HID + off];
    dout[OUT_TAIL + (size_t)seg * 65536 + off] = v;
}

// ============================================================================
extern "C" void kernel_launch(void* const* d_in, const int* in_sizes, int n_in,
                              void* d_out, int out_size)
{
    const float* x    = (const float*)d_in[0];
    const float* Wih0 = (const float*)d_in[1];
    const float* bih0 = (const float*)d_in[2];
    const float* Whh0 = (const float*)d_in[3];
    const float* bhh0 = (const float*)d_in[4];
    const float* Wih1 = (const float*)d_in[5];
    const float* bih1 = (const float*)d_in[6];
    const float* Whh1 = (const float*)d_in[7];
    const float* bhh1 = (const float*)d_in[8];
    float* out = (float*)d_out;

    cudaFuncSetAttribute(gemm_mma_kernel,
                         cudaFuncAttributeMaxDynamicSharedMemorySize, 2 * GSTAGE);
    cudaFuncSetAttribute(lstm_layer_mma_kernel,
                         cudaFuncAttributeMaxDynamicSharedMemorySize, R_SMEM);

    __nv_bfloat16 *xhi, *xlo, *h0hi, *h0lo;
    __nv_bfloat16 *w0h, *w0l, *w1h, *w1l, *wh0h, *wh0l, *wh1h, *wh1l;
    cudaGetSymbolAddress((void**)&xhi,  g_xhi);
    cudaGetSymbolAddress((void**)&xlo,  g_xlo);
    cudaGetSymbolAddress((void**)&h0hi, g_h0hi);
    cudaGetSymbolAddress((void**)&h0lo, g_h0lo);
    cudaGetSymbolAddress((void**)&w0h,  g_w0hiT);
    cudaGetSymbolAddress((void**)&w0l,  g_w0loT);
    cudaGetSymbolAddress((void**)&w1h,  g_w1hiT);
    cudaGetSymbolAddress((void**)&w1l,  g_w1loT);
    cudaGetSymbolAddress((void**)&wh0h, g_wh0hiT);
    cudaGetSymbolAddress((void**)&wh0l, g_wh0loT);
    cudaGetSymbolAddress((void**)&wh1h, g_wh1hiT);
    cudaGetSymbolAddress((void**)&wh1l, g_wh1loT);

    const int NX = MROWS * HID;
    dim3 tg(NG / 32, HID / 32);          // transpose grid
    dim3 gg(NG / 128, MROWS / 128);      // gemm grid: 32 x 256

    // Phase 0: conversions
    split_kernel<<<NX / 256, 256>>>(x, xhi, xlo, NX);
    transpose_split_kernel<<<tg, dim3(32, 8)>>>(Wih0, w0h, w0l);
    transpose_split_kernel<<<tg, dim3(32, 8)>>>(Wih1, w1h, w1l);
    transpose_split_kernel<<<tg, dim3(32, 8)>>>(Whh0, wh0h, wh0l);
    transpose_split_kernel<<<tg, dim3(32, 8)>>>(Whh1, wh1h, wh1l);

    // Phase 1: G0 = x @ Wih0 + bih0 + bhh0   (tensor cores)
    gemm_mma_kernel<<<gg, 256, 2 * GSTAGE>>>(xhi, xlo, w0h, w0l, bih0, bhh0);

    // Phase 2: layer-0 recurrence (persistent, tensor cores)
    lstm_layer_mma_kernel<<<STEP_CTAS, 256, R_SMEM>>>(wh0h, wh0l, 0, out);

    // Phase 3: G1 = h0_seq @ Wih1 + bih1 + bhh1   (tensor cores)
    gemm_mma_kernel<<<gg, 256, 2 * GSTAGE>>>(h0hi, h0lo, w1h, w1l, bih1, bhh1);

    // Phase 4: layer-1 recurrence (directly into d_out)
    lstm_layer_mma_kernel<<<STEP_CTAS, 256, R_SMEM>>>(wh1h, wh1l, 1, out);

    // Phase 5: h_n / c_n
    finalize_kernel<<<1024, 256>>>(out);
}